// round 12
// baseline (speedup 1.0000x reference)
#include <cuda_runtime.h>
#include <cuda_fp16.h>
#include <cstdint>
#include <math.h>

// ---------------- problem constants ----------------
#define M_TOT   65536
#define FEAT    512
#define F2      1024
#define NAA     21
#define EPSF    1e-6f
#define NT_ROW  533
#define MP_MAX  (NT_ROW * 128)

// ---------------- device scratch ----------------
__device__ __align__(16) __half  g_crdh[(size_t)M_TOT * 48];
__device__ __align__(16) __half  g_h1[(size_t)MP_MAX * F2];
__device__ __align__(16) __half  g_h2[(size_t)MP_MAX * FEAT];
__device__ __align__(16) __half2 g_w1h[(size_t)NAA * 24 * F2];   // [cls][k2<24][n]
__device__ __align__(16) __half2 g_w2h[(size_t)512 * FEAT];      // [k2][n]
__device__ __align__(16) __half2 g_w3h[(size_t)256 * FEAT];
__device__ __align__(16) __half2 g_w4h[(size_t)256 * FEAT];
__device__ __align__(16) float g_bias1[NAA * F2];
__device__ int g_counts[NAA];
__device__ int g_fill[NAA];
__device__ int g_offs[NAA];
__device__ int g_perm[MP_MAX];
__device__ int g_tile_aa[NT_ROW];

// ---------------- helpers ----------------
__device__ __forceinline__ uint32_t smem_u32(const void* p) {
    uint32_t a;
    asm("{ .reg .u64 t; cvta.to.shared.u64 t, %1; cvt.u32.u64 %0, t; }" : "=r"(a) : "l"(p));
    return a;
}
__device__ __forceinline__ void cp16(uint32_t dst, const void* src) {
    asm volatile("cp.async.cg.shared.global [%0], [%1], 16;" :: "r"(dst), "l"(src));
}
#define CP_COMMIT() asm volatile("cp.async.commit_group;" ::: "memory")
#define CP_WAIT(n)  asm volatile("cp.async.wait_group %0;" :: "n"(n) : "memory")

__device__ __forceinline__ void mma16(float* c, const uint32_t* a, const uint32_t* b) {
    asm volatile(
        "mma.sync.aligned.m16n8k16.row.col.f32.f16.f16.f32 "
        "{%0,%1,%2,%3}, {%4,%5,%6,%7}, {%8,%9}, {%0,%1,%2,%3};"
        : "+f"(c[0]), "+f"(c[1]), "+f"(c[2]), "+f"(c[3])
        : "r"(a[0]), "r"(a[1]), "r"(a[2]), "r"(a[3]), "r"(b[0]), "r"(b[1]));
}
__device__ __forceinline__ void ldmA(uint32_t* r, uint32_t addr) {
    asm volatile("ldmatrix.sync.aligned.m8n8.x4.shared.b16 {%0,%1,%2,%3}, [%4];"
        : "=r"(r[0]), "=r"(r[1]), "=r"(r[2]), "=r"(r[3]) : "r"(addr));
}

// smem strides (in half2 words)
#define SA2   20     // layers 2-4: A row = 16 data + 4 pad
#define SA1   28     // layer  1 : A row = 24 data + 4 pad
#define SBN   264    // B row = 256 data + 8 pad
#define SH3   260    // fused h3 tile row = 256 data + 4 pad
#define A_H2  (128 * SA2)
#define B_H2  (16 * SBN)
#define ST_H2 (A_H2 + B_H2)
#define SMEM_G_BYTES  (3 * ST_H2 * 4)                      // 81408 B
#define SMEM_1_BYTES  ((128 * SA1 + 24 * SBN) * 4)         // 39680 B
#define SMEM_34_BYTES ((3 * ST_H2 + 128 * SH3) * 4)        // 214528 B

// ---------------- frame kernel (warp-aggregated histogram) ----------------
__global__ void frame_kernel(const int* __restrict__ aa,
                             const float* __restrict__ pos14,
                             const int* __restrict__ mask) {
    int m = blockIdx.x * blockDim.x + threadIdx.x;
    if (m >= M_TOT) return;
    int lane = threadIdx.x & 31;
    int a = aa[m];
    unsigned mm = __match_any_sync(0xFFFFFFFFu, a);
    if (lane == __ffs(mm) - 1) atomicAdd(&g_counts[a], __popc(mm));

    const float* p = pos14 + (size_t)m * 42;
    float cx = p[3], cy = p[4], cz = p[5];
    float v1x = p[6] - cx, v1y = p[7] - cy, v1z = p[8] - cz;
    float n1 = sqrtf(v1x*v1x + v1y*v1y + v1z*v1z) + EPSF;
    float e1x = v1x / n1, e1y = v1y / n1, e1z = v1z / n1;
    float v2x = p[0] - cx, v2y = p[1] - cy, v2z = p[2] - cz;
    float d  = e1x*v2x + e1y*v2y + e1z*v2z;
    float u2x = v2x - d*e1x, u2y = v2y - d*e1y, u2z = v2z - d*e1z;
    float n2 = sqrtf(u2x*u2x + u2y*u2y + u2z*u2z) + EPSF;
    float e2x = u2x / n2, e2y = u2y / n2, e2z = u2z / n2;
    float e3x = e1y*e2z - e1z*e2y;
    float e3y = e1z*e2x - e1x*e2z;
    float e3z = e1x*e2y - e1y*e2x;

    __half* out = g_crdh + (size_t)m * 48;
#pragma unroll
    for (int at = 0; at < 14; at++) {
        float qx = p[at*3+0] - cx, qy = p[at*3+1] - cy, qz = p[at*3+2] - cz;
        bool mk = mask[m*14 + at] != 0;
        out[at*3+0] = __float2half_rn(mk ? (e1x*qx + e1y*qy + e1z*qz) : 0.f);
        out[at*3+1] = __float2half_rn(mk ? (e2x*qx + e2y*qy + e2z*qz) : 0.f);
        out[at*3+2] = __float2half_rn(mk ? (e3x*qx + e3y*qy + e3z*qz) : 0.f);
    }
#pragma unroll
    for (int k = 42; k < 48; k++) out[k] = __float2half_rn(0.f);
}

__global__ void plan_kernel() {
    int off = 0, t = 0;
    for (int a = 0; a < NAA; a++) {
        g_offs[a] = off;
        int nt = (g_counts[a] + 127) >> 7;
        for (int i = 0; i < nt; i++) g_tile_aa[t++] = a;
        off += nt << 7;
    }
    for (; t < NT_ROW; t++) g_tile_aa[t] = -1;
}

// warp-aggregated scatter
__global__ void scatter_kernel(const int* __restrict__ aa) {
    int m = blockIdx.x * blockDim.x + threadIdx.x;
    if (m >= M_TOT) return;
    int lane = threadIdx.x & 31;
    int a = aa[m];
    unsigned mm = __match_any_sync(0xFFFFFFFFu, a);
    int ldr = __ffs(mm) - 1;
    int rank = __popc(mm & ((1u << lane) - 1));
    int base = 0;
    if (lane == ldr) base = atomicAdd(&g_fill[a], __popc(mm));
    base = __shfl_sync(mm, base, ldr);
    g_perm[g_offs[a] + base + rank] = m;
}

// ---------------- merged prep kernel ----------------
// block ranges: [0,267) perm/count init | [267,771) w1h | [771,1283) packw | [1283,1287) bias1
#define NB_INIT 267
#define NB_W1H  504
#define NB_PACK 512
#define NB_BIAS 4
#define NB_PREP (NB_INIT + NB_W1H + NB_PACK + NB_BIAS)

__global__ __launch_bounds__(256) void prep_kernel(const float* __restrict__ w1,
                                                   const float* __restrict__ b1,
                                                   const float* __restrict__ w2,
                                                   const float* __restrict__ w3,
                                                   const float* __restrict__ w4,
                                                   const float* __restrict__ embed) {
    __shared__ float emb[NAA * FEAT];
    int bid = blockIdx.x, tid = threadIdx.x;

    if (bid < NB_INIT) {
        int i = bid * 256 + tid;
        if (i < MP_MAX) g_perm[i] = -1;
        if (i < NAA) { g_counts[i] = 0; g_fill[i] = 0; }
        return;
    }
    if (bid < NB_INIT + NB_W1H) {
        int i0 = ((bid - NB_INIT) * 256 + tid) * 4;
        int n = i0 & (F2 - 1);
        int r = i0 >> 10;
        int k2 = r % 24, cls = r / 24;
        int kr0 = cls * 42 + 2 * k2, kr1 = kr0 + 1;
        __half2 v[4];
#pragma unroll
        for (int q = 0; q < 4; q++) {
            float a = (2 * k2     < 42) ? w1[(size_t)kr0 * F2 + n + q] : 0.f;
            float b = (2 * k2 + 1 < 42) ? w1[(size_t)kr1 * F2 + n + q] : 0.f;
            v[q] = __floats2half2_rn(a, b);
        }
        *(uint4*)&g_w1h[i0] = *(uint4*)v;
        return;
    }
    if (bid < NB_INIT + NB_W1H + NB_PACK) {
        int b = bid - NB_INIT - NB_W1H;
        const float* src; __half2* dst; int lb;
        if (b < 256)      { src = w2; dst = g_w2h; lb = b; }
        else if (b < 384) { src = w3; dst = g_w3h; lb = b - 256; }
        else              { src = w4; dst = g_w4h; lb = b - 384; }
        int i0 = (lb * 256 + tid) * 4;
        int n = i0 & (FEAT - 1), k2 = i0 >> 9;
        __half2 v[4];
#pragma unroll
        for (int q = 0; q < 4; q++)
            v[q] = __floats2half2_rn(src[(size_t)(2 * k2) * FEAT + n + q],
                                     src[(size_t)(2 * k2 + 1) * FEAT + n + q]);
        *(uint4*)&dst[i0] = *(uint4*)v;
        return;
    }
    // bias1: bias1_aa[a][j] = b1[j] + sum_k embed[a][k] * w1[882+k][j]
    {
        for (int t = tid; t < NAA * FEAT; t += 256) emb[t] = embed[t];
        __syncthreads();
        int j = (bid - NB_INIT - NB_W1H - NB_PACK) * 256 + tid;   // 0..1023
        float acc[NAA];
#pragma unroll
        for (int a = 0; a < NAA; a++) acc[a] = 0.f;
        for (int k = 0; k < FEAT; k++) {
            float wv = w1[(size_t)(882 + k) * F2 + j];
#pragma unroll
            for (int a = 0; a < NAA; a++) acc[a] += emb[a * FEAT + k] * wv;
        }
        float bj = b1[j];
#pragma unroll
        for (int a = 0; a < NAA; a++) g_bias1[a * F2 + j] = bj + acc[a];
    }
}

// ---------------- GEMM layer 2: CTA 128x256, K=1024, half in/out + relu ----------------
__global__ __launch_bounds__(256, 1) void gemm2_mma(const __half* __restrict__ A,
                                                    const __half2* __restrict__ W,
                                                    const float* __restrict__ bias,
                                                    __half* __restrict__ C) {
    int by = blockIdx.y;
    if (g_tile_aa[by] < 0) return;
    extern __shared__ __align__(16) char smc[];
    __half2* sm = (__half2*)smc;

    int tid = threadIdx.x;
    int bx = blockIdx.x;
    int rowbase = by * 128;
    int c_base = bx * 256;

    int wid = tid >> 5, lane = tid & 31;
    int wm = wid & 1, wn = wid >> 1;
    int gid = lane >> 2, tig = lane & 3;
    int lrow = lane & 15, lkg = lane >> 4;

    const __half* Ab = A + (size_t)rowbase * 1024;
    const int NS = 32;

    float acc[4][8][4];
#pragma unroll
    for (int i = 0; i < 4; i++)
#pragma unroll
        for (int j = 0; j < 8; j++)
#pragma unroll
            for (int q = 0; q < 4; q++) acc[i][j][q] = 0.f;

    auto load_stage = [&](int s) {
        int buf = s % 3;
        __half2* As = sm + buf * ST_H2;
        __half2* Bs = As + A_H2;
#pragma unroll
        for (int i = 0; i < 2; i++) {
            int f = tid + i * 256;
            int row = f >> 2, sg = f & 3;
            cp16(smem_u32(&As[row * SA2 + sg * 4]),
                 Ab + (size_t)row * 1024 + s * 32 + sg * 8);
        }
#pragma unroll
        for (int i = 0; i < 4; i++) {
            int f = tid + i * 256;
            int kr = f >> 6, sg = f & 63;
            cp16(smem_u32(&Bs[kr * SBN + sg * 4]),
                 W + (size_t)(s * 16 + kr) * FEAT + c_base + sg * 4);
        }
    };

    load_stage(0); CP_COMMIT();
    load_stage(1); CP_COMMIT();

    for (int s = 0; s < NS; s++) {
        CP_WAIT(1);
        __syncthreads();
        if (s + 2 < NS) load_stage(s + 2);
        CP_COMMIT();

        int buf = s % 3;
        __half2* As = sm + buf * ST_H2;
        const uint32_t* Bs32 = (const uint32_t*)(As + A_H2);
        uint32_t As_addr = smem_u32(As);
#pragma unroll
        for (int kt = 0; kt < 2; kt++) {
            uint32_t af[4][4], bf[8][2];
#pragma unroll
            for (int mt = 0; mt < 4; mt++) {
                int am = wm * 64 + mt * 16 + lrow;
                ldmA(af[mt], As_addr + am * (SA2 * 4) + kt * 32 + lkg * 16);
            }
#pragma unroll
            for (int nt = 0; nt < 8; nt++) {
                int bn = wn * 64 + nt * 8 + gid;
                int k2 = kt * 8 + tig;
                bf[nt][0] = Bs32[k2 * SBN + bn];
                bf[nt][1] = Bs32[(k2 + 4) * SBN + bn];
            }
#pragma unroll
            for (int mt = 0; mt < 4; mt++)
#pragma unroll
                for (int nt = 0; nt < 8; nt++)
                    mma16(acc[mt][nt], af[mt], bf[nt]);
        }
        __syncthreads();
    }

#pragma unroll
    for (int mt = 0; mt < 4; mt++) {
        int r0 = rowbase + wm * 64 + mt * 16 + gid;
        __half* d0 = C + (size_t)r0 * FEAT;
        __half* d1 = d0 + (size_t)8 * FEAT;
#pragma unroll
        for (int nt = 0; nt < 8; nt++) {
            int c = c_base + wn * 64 + nt * 8 + tig * 2;
            float bx0 = bias[c], bx1 = bias[c + 1];
            *(__half2*)(d0 + c) = __floats2half2_rn(fmaxf(acc[mt][nt][0] + bx0, 0.f),
                                                    fmaxf(acc[mt][nt][1] + bx1, 0.f));
            *(__half2*)(d1 + c) = __floats2half2_rn(fmaxf(acc[mt][nt][2] + bx0, 0.f),
                                                    fmaxf(acc[mt][nt][3] + bx1, 0.f));
        }
    }
}

// ---------------- fused layers 3+4: h3 lives in smem ----------------
__global__ __launch_bounds__(256, 1) void gemm34_mma(const __half* __restrict__ A2,
                                                     const __half2* __restrict__ W3,
                                                     const float* __restrict__ b3,
                                                     const __half2* __restrict__ W4,
                                                     const float* __restrict__ b4,
                                                     float* __restrict__ out) {
    int by = blockIdx.x;
    if (g_tile_aa[by] < 0) return;
    extern __shared__ __align__(16) char smc[];
    __half2* sm = (__half2*)smc;
    __half2* h3 = sm + 3 * ST_H2;

    int tid = threadIdx.x;
    int rowbase = by * 128;
    int wid = tid >> 5, lane = tid & 31;
    int wm = wid & 1, wn = wid >> 1;
    int gid = lane >> 2, tig = lane & 3;
    int lrow = lane & 15, lkg = lane >> 4;

    const __half* Ab = A2 + (size_t)rowbase * 512;
    const int NS = 16;

    // ---- layer 3: two N-halves -> h3 smem ----
    for (int hf = 0; hf < 2; hf++) {
        int c_base = hf * 256;
        float acc[4][8][4];
#pragma unroll
        for (int i = 0; i < 4; i++)
#pragma unroll
            for (int j = 0; j < 8; j++)
#pragma unroll
                for (int q = 0; q < 4; q++) acc[i][j][q] = 0.f;

        auto load_stage3 = [&](int s) {
            int buf = s % 3;
            __half2* As = sm + buf * ST_H2;
            __half2* Bs = As + A_H2;
#pragma unroll
            for (int i = 0; i < 2; i++) {
                int f = tid + i * 256;
                int row = f >> 2, sg = f & 3;
                cp16(smem_u32(&As[row * SA2 + sg * 4]),
                     Ab + (size_t)row * 512 + s * 32 + sg * 8);
            }
#pragma unroll
            for (int i = 0; i < 4; i++) {
                int f = tid + i * 256;
                int kr = f >> 6, sg = f & 63;
                cp16(smem_u32(&Bs[kr * SBN + sg * 4]),
                     W3 + (size_t)(s * 16 + kr) * FEAT + c_base + sg * 4);
            }
        };

        load_stage3(0); CP_COMMIT();
        load_stage3(1); CP_COMMIT();

        for (int s = 0; s < NS; s++) {
            CP_WAIT(1);
            __syncthreads();
            if (s + 2 < NS) load_stage3(s + 2);
            CP_COMMIT();

            int buf = s % 3;
            __half2* As = sm + buf * ST_H2;
            const uint32_t* Bs32 = (const uint32_t*)(As + A_H2);
            uint32_t As_addr = smem_u32(As);
#pragma unroll
            for (int kt = 0; kt < 2; kt++) {
                uint32_t af[4][4], bf[8][2];
#pragma unroll
                for (int mt = 0; mt < 4; mt++) {
                    int am = wm * 64 + mt * 16 + lrow;
                    ldmA(af[mt], As_addr + am * (SA2 * 4) + kt * 32 + lkg * 16);
                }
#pragma unroll
                for (int nt = 0; nt < 8; nt++) {
                    int bn = wn * 64 + nt * 8 + gid;
                    int k2 = kt * 8 + tig;
                    bf[nt][0] = Bs32[k2 * SBN + bn];
                    bf[nt][1] = Bs32[(k2 + 4) * SBN + bn];
                }
#pragma unroll
                for (int mt = 0; mt < 4; mt++)
#pragma unroll
                    for (int nt = 0; nt < 8; nt++)
                        mma16(acc[mt][nt], af[mt], bf[nt]);
            }
            __syncthreads();
        }
        CP_WAIT(0);

        // epilogue -> h3 smem (relu + bias3, fp16)
#pragma unroll
        for (int mt = 0; mt < 4; mt++) {
            int r0 = wm * 64 + mt * 16 + gid;
            int r1 = r0 + 8;
#pragma unroll
            for (int nt = 0; nt < 8; nt++) {
                int c = c_base + wn * 64 + nt * 8 + tig * 2;
                float bx0 = b3[c], bx1 = b3[c + 1];
                int c2 = c >> 1;
                h3[r0 * SH3 + c2] = __floats2half2_rn(fmaxf(acc[mt][nt][0] + bx0, 0.f),
                                                      fmaxf(acc[mt][nt][1] + bx1, 0.f));
                h3[r1 * SH3 + c2] = __floats2half2_rn(fmaxf(acc[mt][nt][2] + bx0, 0.f),
                                                      fmaxf(acc[mt][nt][3] + bx1, 0.f));
            }
        }
        __syncthreads();
    }

    // ---- layer 4: A from h3 smem, two N-halves, fp32 scatter out ----
    uint32_t h3_addr = smem_u32(h3);
    for (int hf = 0; hf < 2; hf++) {
        int c_base = hf * 256;
        float acc[4][8][4];
#pragma unroll
        for (int i = 0; i < 4; i++)
#pragma unroll
            for (int j = 0; j < 8; j++)
#pragma unroll
                for (int q = 0; q < 4; q++) acc[i][j][q] = 0.f;

        auto load_stage4 = [&](int s) {
            int buf = s % 3;
            __half2* Bs = sm + buf * B_H2;
#pragma unroll
            for (int i = 0; i < 4; i++) {
                int f = tid + i * 256;
                int kr = f >> 6, sg = f & 63;
                cp16(smem_u32(&Bs[kr * SBN + sg * 4]),
                     W4 + (size_t)(s * 16 + kr) * FEAT + c_base + sg * 4);
            }
        };

        load_stage4(0); CP_COMMIT();
        load_stage4(1); CP_COMMIT();

        for (int s = 0; s < NS; s++) {
            CP_WAIT(1);
            __syncthreads();
            if (s + 2 < NS) load_stage4(s + 2);
            CP_COMMIT();

            const uint32_t* Bs32 = (const uint32_t*)(sm + (s % 3) * B_H2);
#pragma unroll
            for (int kt = 0; kt < 2; kt++) {
                uint32_t af[4][4], bf[8][2];
#pragma unroll
                for (int mt = 0; mt < 4; mt++) {
                    int am = wm * 64 + mt * 16 + lrow;
                    ldmA(af[mt], h3_addr + am * (SH3 * 4) + s * 64 + kt * 32 + lkg * 16);
                }
#pragma unroll
                for (int nt = 0; nt < 8; nt++) {
                    int bn = wn * 64 + nt * 8 + gid;
                    int k2 = kt * 8 + tig;
                    bf[nt][0] = Bs32[k2 * SBN + bn];
                    bf[nt][1] = Bs32[(k2 + 4) * SBN + bn];
                }
#pragma unroll
                for (int mt = 0; mt < 4; mt++)
#pragma unroll
                    for (int nt = 0; nt < 8; nt++)
                        mma16(acc[mt][nt], af[mt], bf[nt]);
            }
            __syncthreads();
        }
        CP_WAIT(0);

        // epilogue: scatter fp32 rows to out
#pragma unroll
        for (int mt = 0; mt < 4; mt++) {
            int r0 = rowbase + wm * 64 + mt * 16 + gid;
            int r1 = r0 + 8;
            int m0 = g_perm[r0], m1 = g_perm[r1];
            float* d0 = (m0 >= 0) ? out + (size_t)m0 * FEAT : nullptr;
            float* d1 = (m1 >= 0) ? out + (size_t)m1 * FEAT : nullptr;
#pragma unroll
            for (int nt = 0; nt < 8; nt++) {
                int c = c_base + wn * 64 + nt * 8 + tig * 2;
                float bx0 = b4[c], bx1 = b4[c + 1];
                if (d0) { float2 v; v.x = acc[mt][nt][0] + bx0; v.y = acc[mt][nt][1] + bx1;
                          *(float2*)(d0 + c) = v; }
                if (d1) { float2 v; v.x = acc[mt][nt][2] + bx0; v.y = acc[mt][nt][3] + bx1;
                          *(float2*)(d1 + c) = v; }
            }
        }
        __syncthreads();
    }
}

// ---------------- GEMM layer 1: gathered A (K=48), per-class W, CTA 128x256 ----------------
__global__ __launch_bounds__(256, 1) void gemm1_mma() {
    int by = blockIdx.y;
    int cls = g_tile_aa[by];
    if (cls < 0) return;
    extern __shared__ __align__(16) char smc[];
    __half2* As = (__half2*)smc;            // 128 x SA1
    __half2* Bs = As + 128 * SA1;           // 24 x SBN

    int tid = threadIdx.x;
    int bx = blockIdx.x;                    // 0..3 over N=1024
    int rowbase = by * 128;
    int c_base = bx * 256;

    int wid = tid >> 5, lane = tid & 31;
    int wm = wid & 1, wn = wid >> 1;
    int gid = lane >> 2, tig = lane & 3;

#pragma unroll
    for (int i = 0; i < 3; i++) {
        int f = tid + i * 256;
        int row = f / 6, j = f % 6;
        int m = g_perm[rowbase + row]; if (m < 0) m = 0;
        cp16(smem_u32(&As[row * SA1 + j * 4]), g_crdh + (size_t)m * 48 + j * 8);
    }
    const __half2* Wb = g_w1h + (size_t)cls * 24 * F2;
#pragma unroll
    for (int i = 0; i < 6; i++) {
        int f = tid + i * 256;
        int kr = f >> 6, sg = f & 63;
        cp16(smem_u32(&Bs[kr * SBN + sg * 4]), Wb + (size_t)kr * F2 + c_base + sg * 4);
    }
    CP_COMMIT();
    CP_WAIT(0);
    __syncthreads();

    float acc[4][8][4];
#pragma unroll
    for (int i = 0; i < 4; i++)
#pragma unroll
        for (int j = 0; j < 8; j++)
#pragma unroll
            for (int q = 0; q < 4; q++) acc[i][j][q] = 0.f;

    const uint32_t* Bs32 = (const uint32_t*)Bs;
    uint32_t As_addr = smem_u32(As);
    int lrow = lane & 15, lkg = lane >> 4;
#pragma unroll
    for (int kt = 0; kt < 3; kt++) {
        uint32_t af[4][4], bf[8][2];
#pragma unroll
        for (int mt = 0; mt < 4; mt++) {
            int am = wm * 64 + mt * 16 + lrow;
            ldmA(af[mt], As_addr + am * (SA1 * 4) + kt * 32 + lkg * 16);
        }
#pragma unroll
        for (int nt = 0; nt < 8; nt++) {
            int bn = wn * 64 + nt * 8 + gid;
            int k2 = kt * 8 + tig;
            bf[nt][0] = Bs32[k2 * SBN + bn];
            bf[nt][1] = Bs32[(k2 + 4) * SBN + bn];
        }
#pragma unroll
        for (int mt = 0; mt < 4; mt++)
#pragma unroll
            for (int nt = 0; nt < 8; nt++)
                mma16(acc[mt][nt], af[mt], bf[nt]);
    }

    const float* bp = g_bias1 + cls * F2;
#pragma unroll
    for (int mt = 0; mt < 4; mt++) {
        int r0 = rowbase + wm * 64 + mt * 16 + gid;
        __half* d0 = g_h1 + (size_t)r0 * F2;
        __half* d1 = d0 + (size_t)8 * F2;
#pragma unroll
        for (int nt = 0; nt < 8; nt++) {
            int c = c_base + wn * 64 + nt * 8 + tig * 2;
            float bx0 = bp[c], bx1 = bp[c + 1];
            *(__half2*)(d0 + c) = __floats2half2_rn(fmaxf(acc[mt][nt][0] + bx0, 0.f),
                                                    fmaxf(acc[mt][nt][1] + bx1, 0.f));
            *(__half2*)(d1 + c) = __floats2half2_rn(fmaxf(acc[mt][nt][2] + bx0, 0.f),
                                                    fmaxf(acc[mt][nt][3] + bx1, 0.f));
        }
    }
}

// ---------------- launch ----------------
extern "C" void kernel_launch(void* const* d_in, const int* in_sizes, int n_in,
                              void* d_out, int out_size) {
    const int*   aa    = (const int*)  d_in[0];
    const float* pos14 = (const float*)d_in[1];
    const int*   mask  = (const int*)  d_in[2];
    const float* embed = (const float*)d_in[3];
    const float* w1    = (const float*)d_in[4];
    const float* b1    = (const float*)d_in[5];
    const float* w2    = (const float*)d_in[6];
    const float* b2    = (const float*)d_in[7];
    const float* w3    = (const float*)d_in[8];
    const float* b3    = (const float*)d_in[9];
    const float* w4    = (const float*)d_in[10];
    const float* b4    = (const float*)d_in[11];
    float* out = (float*)d_out;

    void *p_h1, *p_h2, *p_w2h, *p_w3h, *p_w4h;
    cudaGetSymbolAddress(&p_h1, g_h1);
    cudaGetSymbolAddress(&p_h2, g_h2);
    cudaGetSymbolAddress(&p_w2h, g_w2h);
    cudaGetSymbolAddress(&p_w3h, g_w3h);
    cudaGetSymbolAddress(&p_w4h, g_w4h);

    cudaFuncSetAttribute(gemm1_mma, cudaFuncAttributeMaxDynamicSharedMemorySize, SMEM_1_BYTES);
    cudaFuncSetAttribute(gemm2_mma, cudaFuncAttributeMaxDynamicSharedMemorySize, SMEM_G_BYTES);
    cudaFuncSetAttribute(gemm34_mma, cudaFuncAttributeMaxDynamicSharedMemorySize, SMEM_34_BYTES);

    prep_kernel<<<NB_PREP, 256>>>(w1, b1, w2, w3, w4, embed);
    frame_kernel<<<M_TOT / 256, 256>>>(aa, pos14, mask);
    plan_kernel<<<1, 1>>>();
    scatter_kernel<<<M_TOT / 256, 256>>>(aa);

    gemm1_mma<<<dim3(4, NT_ROW), 256, SMEM_1_BYTES>>>();
    gemm2_mma<<<dim3(2, NT_ROW), 256, SMEM_G_BYTES>>>((const __half*)p_h1, (const __half2*)p_w2h, b2, (__half*)p_h2);
    gemm34_mma<<<NT_ROW, 256, SMEM_34_BYTES>>>((const __half*)p_h2, (const __half2*)p_w3h, b3,
                                               (const __half2*)p_w4h, b4, out);
    (void)in_sizes; (void)n_in; (void)out_size;
}